// round 4
// baseline (speedup 1.0000x reference)
#include <cuda_runtime.h>
#include <cuda_fp16.h>
#include <cstdint>

// ---------------------------------------------------------------------------
// Problem constants: B=8, L=2048, D=1024, FF_MULT=2
//   M = B*L = 16384 rows, D = 1024
// ---------------------------------------------------------------------------
#define MROWS 16384
#define DDIM  1024
#define EPS_LN 1e-6f

// ---------------------------------------------------------------------------
// Scratch (device globals; allocation-free rule)
// ---------------------------------------------------------------------------
__device__ __half g_norm  [MROWS * 1024];     // LN1 output (fp16)
__device__ __half g_H12   [MROWS * 2048];     // gelu(norm @ [w1|w1b])
__device__ float  g_x1    [MROWS * 1024];     // x + gate_msa * ssm_out
__device__ __half g_ffnorm[MROWS * 1024];     // LN2 output
__device__ __half g_H3    [MROWS * 2048];     // gelu_tanh(ffnorm @ ff_w1)
__device__ __half g_w1cat [1024 * 2048];      // [ssm_w1 | bwd_w1] fp16
__device__ __half g_w2cat [2048 * 1024];      // [ssm_w2 ; bwd_w2] fp16
__device__ __half g_ffw1h [1024 * 2048];
__device__ __half g_ffw2h [2048 * 1024];
__device__ float  g_emb   [8 * 3072];         // silu(t)@ada_w + ada_b
__device__ float  g_ffada [8 * 3072];         // silu(t)@ffada_w + ffada_b

// ---------------------------------------------------------------------------
// Helpers
// ---------------------------------------------------------------------------
__device__ __forceinline__ uint32_t smem_u32(const void* p) {
    return (uint32_t)__cvta_generic_to_shared(p);
}
__device__ __forceinline__ float gelu_erf_f(float x) {
    return 0.5f * x * (1.f + erff(x * 0.70710678118654752f));
}
__device__ __forceinline__ float gelu_tanh_f(float x) {
    float x3 = x * x * x;
    return 0.5f * x * (1.f + tanhf(0.79788456080286536f * (x + 0.044715f * x3)));
}

// ---------------------------------------------------------------------------
// fp32 -> fp16 strided converter (weight concat)
// ---------------------------------------------------------------------------
__global__ void convert_strided(__half* __restrict__ dst, const float* __restrict__ src,
                                int rows, int cols, int dst_stride, int dst_off)
{
    int idx = blockIdx.x * blockDim.x + threadIdx.x;
    int i = idx * 4;
    if (i >= rows * cols) return;
    float4 v = *(const float4*)(src + i);
    int r = i / cols, c = i % cols;
    __half* d = dst + (size_t)r * dst_stride + dst_off + c;
    *(__half2*)(d)     = __floats2half2_rn(v.x, v.y);
    *(__half2*)(d + 2) = __floats2half2_rn(v.z, v.w);
}

// ---------------------------------------------------------------------------
// adaLN: st = silu(t)  (8x1024); emb = st@ada_w + ada_b; ffada = st@ffada_w + ffada_b
// ---------------------------------------------------------------------------
__global__ __launch_bounds__(256)
void adaln_kernel(const float* __restrict__ t,
                  const float* __restrict__ ada_w,  const float* __restrict__ ada_b,
                  const float* __restrict__ ffada_w,const float* __restrict__ ffada_b,
                  float* __restrict__ emb, float* __restrict__ ffada)
{
    __shared__ float st[8][1024];
    int tid = threadIdx.x;
    for (int i = tid; i < 8 * 1024; i += 256) {
        float v = t[i];
        st[i >> 10][i & 1023] = v / (1.f + expf(-v));
    }
    __syncthreads();

    int col = blockIdx.x * 256 + tid;          // 0..6143
    const float* W; const float* Bv; float* O; int c;
    if (col < 3072) { W = ada_w;   Bv = ada_b;   O = emb;   c = col; }
    else            { W = ffada_w; Bv = ffada_b; O = ffada; c = col - 3072; }

    float acc[8];
    #pragma unroll
    for (int b = 0; b < 8; b++) acc[b] = 0.f;
    #pragma unroll 4
    for (int k = 0; k < 1024; k++) {
        float wv = W[(size_t)k * 3072 + c];
        #pragma unroll
        for (int b = 0; b < 8; b++) acc[b] += st[b][k] * wv;
    }
    float bv = Bv[c];
    #pragma unroll
    for (int b = 0; b < 8; b++) O[b * 3072 + c] = acc[b] + bv;
}

// ---------------------------------------------------------------------------
// LayerNorm + adaLN modulation (+ optional mask), fp32 in -> fp16 out
//   mask is int32 (jax bool promoted by the harness)
// ---------------------------------------------------------------------------
template<bool MASKED>
__global__ __launch_bounds__(256)
void ln_mod_kernel(const float* __restrict__ x, const float* __restrict__ ada,
                   const int* __restrict__ maskp, __half* __restrict__ out)
{
    int row = blockIdx.x;
    int tid = threadIdx.x;
    const float* xr = x + (size_t)row * 1024;
    float4 xv = ((const float4*)xr)[tid];
    float s = xv.x + xv.y + xv.z + xv.w;
    float q = xv.x * xv.x + xv.y * xv.y + xv.z * xv.z + xv.w * xv.w;
    #pragma unroll
    for (int o = 16; o; o >>= 1) {
        s += __shfl_xor_sync(0xffffffffu, s, o);
        q += __shfl_xor_sync(0xffffffffu, q, o);
    }
    __shared__ float ss[8], sq[8];
    __shared__ float mu_s, rs_s;
    int w = tid >> 5;
    if ((tid & 31) == 0) { ss[w] = s; sq[w] = q; }
    __syncthreads();
    if (tid == 0) {
        float S = 0.f, Q = 0.f;
        #pragma unroll
        for (int i = 0; i < 8; i++) { S += ss[i]; Q += sq[i]; }
        float mu = S * (1.f / 1024.f);
        float var = Q * (1.f / 1024.f) - mu * mu;
        mu_s = mu; rs_s = rsqrtf(var + EPS_LN);
    }
    __syncthreads();

    __half* orow = out + (size_t)row * 1024;
    if (MASKED && maskp[row] == 0) {
        ((uint2*)orow)[tid] = make_uint2(0u, 0u);   // 4 zero halves
        return;
    }
    float mu = mu_s, rs = rs_s;
    int b = row >> 11;                               // row / 2048
    const float* shp = ada + b * 3072;               // shift
    int c = tid * 4;
    float4 sh4 = *(const float4*)(shp + c);
    float4 sc4 = *(const float4*)(shp + 1024 + c);   // scale
    float o0 = (xv.x - mu) * rs * (1.f + sc4.x) + sh4.x;
    float o1 = (xv.y - mu) * rs * (1.f + sc4.y) + sh4.y;
    float o2 = (xv.z - mu) * rs * (1.f + sc4.z) + sh4.z;
    float o3 = (xv.w - mu) * rs * (1.f + sc4.w) + sh4.w;
    *(__half2*)(orow + c)     = __floats2half2_rn(o0, o1);
    *(__half2*)(orow + c + 2) = __floats2half2_rn(o2, o3);
}

// ---------------------------------------------------------------------------
// fp16 GEMM, fp32 accumulate.  C = epilogue(A[MxK] @ B[KxN])
// Tiles: 128x128x32, 256 threads = 8 warps (4 along M x 2 along N), warp 32x64
// EPI: 0 = gelu_erf(+split bias)        -> half
//      1 = mask*( +b0[c]+b1[c] ), gate, +resid -> float
//      2 = gelu_tanh(+b0[c])            -> half
//      3 = gate*( +b0[c] ) + resid      -> float
// ---------------------------------------------------------------------------
#define BM 128
#define BN 128
#define BK 32
#define PADA 8
#define PADB 8

template<int EPI>
__global__ __launch_bounds__(256, 2)
void gemm_f16(const __half* __restrict__ A, const __half* __restrict__ Bmat,
              int M, int N, int K,
              const float* __restrict__ bias0, const float* __restrict__ bias1, int bsplit,
              const float* __restrict__ resid, const float* __restrict__ ada,
              const int* __restrict__ maskp,
              void* __restrict__ outp)
{
    __shared__ alignas(16) __half As[BM][BK + PADA];   // 128 x 40
    __shared__ alignas(16) __half Bs[BK][BN + PADB];   // 32 x 136

    const int tid  = threadIdx.x;
    const int lane = tid & 31;
    const int warp = tid >> 5;
    const int wm = warp & 3;      // 0..3 -> M offset wm*32
    const int wn = warp >> 2;     // 0..1 -> N offset wn*64
    const int row0 = blockIdx.y * BM;
    const int col0 = blockIdx.x * BN;

    float acc[2][8][4];
    #pragma unroll
    for (int i = 0; i < 2; i++)
        #pragma unroll
        for (int j = 0; j < 8; j++)
            #pragma unroll
            for (int v = 0; v < 4; v++) acc[i][j][v] = 0.f;

    // global load mapping
    const int a_r = tid >> 2;               // 0..63
    const int a_c = (tid & 3) * 8;          // 0,8,16,24
    const int b_r = tid >> 4;               // 0..15
    const int b_c = (tid & 15) * 8;         // 0..120
    const __half* Ap  = A + (size_t)(row0 + a_r) * K + a_c;
    const __half* Ap2 = Ap + (size_t)64 * K;
    const __half* Bp  = Bmat + (size_t)b_r * N + col0 + b_c;
    const __half* Bp2 = Bp + (size_t)16 * N;

    int4 ra  = *(const int4*)(Ap);
    int4 ra2 = *(const int4*)(Ap2);
    int4 rb  = *(const int4*)(Bp);
    int4 rb2 = *(const int4*)(Bp2);

    for (int k0 = 0; k0 < K; k0 += BK) {
        *(int4*)&As[a_r][a_c]       = ra;
        *(int4*)&As[a_r + 64][a_c]  = ra2;
        *(int4*)&Bs[b_r][b_c]       = rb;
        *(int4*)&Bs[b_r + 16][b_c]  = rb2;
        __syncthreads();

        if (k0 + BK < K) {
            ra  = *(const int4*)(Ap  + k0 + BK);
            ra2 = *(const int4*)(Ap2 + k0 + BK);
            rb  = *(const int4*)(Bp  + (size_t)(k0 + BK) * N);
            rb2 = *(const int4*)(Bp2 + (size_t)(k0 + BK) * N);
        }

        #pragma unroll
        for (int kk = 0; kk < BK; kk += 16) {
            uint32_t aF[2][4];
            uint32_t bF[8][2];
            #pragma unroll
            for (int i = 0; i < 2; i++) {
                int r = wm * 32 + i * 16 + (lane & 15);
                int c = kk + (lane >> 4) * 8;
                uint32_t addr = smem_u32(&As[r][c]);
                asm volatile("ldmatrix.sync.aligned.m8n8.x4.shared.b16 {%0,%1,%2,%3}, [%4];"
                    : "=r"(aF[i][0]), "=r"(aF[i][1]), "=r"(aF[i][2]), "=r"(aF[i][3])
                    : "r"(addr));
            }
            #pragma unroll
            for (int nt = 0; nt < 4; nt++) {
                int r = kk + (lane & 15);
                int c = wn * 64 + nt * 16 + (lane >> 4) * 8;
                uint32_t addr = smem_u32(&Bs[r][c]);
                asm volatile("ldmatrix.sync.aligned.m8n8.x4.trans.shared.b16 {%0,%1,%2,%3}, [%4];"
                    : "=r"(bF[2*nt][0]), "=r"(bF[2*nt][1]), "=r"(bF[2*nt+1][0]), "=r"(bF[2*nt+1][1])
                    : "r"(addr));
            }
            #pragma unroll
            for (int i = 0; i < 2; i++)
                #pragma unroll
                for (int j = 0; j < 8; j++)
                    asm volatile(
                        "mma.sync.aligned.m16n8k16.row.col.f32.f16.f16.f32 "
                        "{%0,%1,%2,%3}, {%4,%5,%6,%7}, {%8,%9}, {%0,%1,%2,%3};"
                        : "+f"(acc[i][j][0]), "+f"(acc[i][j][1]),
                          "+f"(acc[i][j][2]), "+f"(acc[i][j][3])
                        : "r"(aF[i][0]), "r"(aF[i][1]), "r"(aF[i][2]), "r"(aF[i][3]),
                          "r"(bF[j][0]), "r"(bF[j][1]));
        }
        __syncthreads();
    }

    // ---------------- epilogue ----------------
    const int lr = lane >> 2;          // 0..7
    const int lc = (lane & 3) * 2;     // 0,2,4,6
    #pragma unroll
    for (int i = 0; i < 2; i++) {
        #pragma unroll
        for (int j = 0; j < 8; j++) {
            int col = col0 + wn * 64 + j * 8 + lc;
            #pragma unroll
            for (int h = 0; h < 2; h++) {
                int r = row0 + wm * 32 + i * 16 + lr + h * 8;
                float v0 = acc[i][j][h * 2 + 0];
                float v1 = acc[i][j][h * 2 + 1];
                if (EPI == 0 || EPI == 2) {
                    float b0 = (col     < bsplit) ? bias0[col]           : bias1[col - bsplit];
                    float b1 = (col + 1 < bsplit) ? bias0[col + 1]       : bias1[col + 1 - bsplit];
                    v0 += b0; v1 += b1;
                    if (EPI == 0) { v0 = gelu_erf_f(v0);  v1 = gelu_erf_f(v1); }
                    else          { v0 = gelu_tanh_f(v0); v1 = gelu_tanh_f(v1); }
                    __half* o = (__half*)outp + (size_t)r * N + col;
                    *(__half2*)o = __floats2half2_rn(v0, v1);
                } else {
                    int bi = r >> 11;  // batch
                    float g0 = ada[bi * 3072 + 2048 + col];
                    float g1 = ada[bi * 3072 + 2048 + col + 1];
                    if (EPI == 1) {
                        v0 += bias0[col]     + bias1[col];
                        v1 += bias0[col + 1] + bias1[col + 1];
                        if (maskp[r] == 0) { v0 = 0.f; v1 = 0.f; }
                    } else {
                        v0 += bias0[col];
                        v1 += bias0[col + 1];
                    }
                    const float* rp = resid + (size_t)r * N + col;
                    float2 res;
                    res.x = rp[0] + g0 * v0;
                    res.y = rp[1] + g1 * v1;
                    *(float2*)((float*)outp + (size_t)r * N + col) = res;
                }
            }
        }
    }
}

// ---------------------------------------------------------------------------
// launch
// ---------------------------------------------------------------------------
extern "C" void kernel_launch(void* const* d_in, const int* in_sizes, int n_in,
                              void* d_out, int out_size)
{
    const float* x       = (const float*)d_in[0];
    const float* t       = (const float*)d_in[1];
    const int*   mask    = (const int*)d_in[2];     // jax bool -> int32
    const float* ada_w   = (const float*)d_in[3];
    const float* ada_b   = (const float*)d_in[4];
    const float* ssm_w1  = (const float*)d_in[5];
    const float* ssm_b1  = (const float*)d_in[6];
    const float* ssm_w2  = (const float*)d_in[7];
    const float* ssm_b2  = (const float*)d_in[8];
    const float* bwd_w1  = (const float*)d_in[9];
    const float* bwd_b1  = (const float*)d_in[10];
    const float* bwd_w2  = (const float*)d_in[11];
    const float* bwd_b2  = (const float*)d_in[12];
    const float* ffada_w = (const float*)d_in[13];
    const float* ffada_b = (const float*)d_in[14];
    const float* ff_w1   = (const float*)d_in[15];
    const float* ff_b1   = (const float*)d_in[16];
    const float* ff_w2   = (const float*)d_in[17];
    const float* ff_b2   = (const float*)d_in[18];
    float* out = (float*)d_out;

    __half *norm_p, *h12_p, *ffnorm_p, *h3_p, *w1c_p, *w2c_p, *fw1_p, *fw2_p;
    float  *x1_p, *emb_p, *ffada_p;
    cudaGetSymbolAddress((void**)&norm_p,   g_norm);
    cudaGetSymbolAddress((void**)&h12_p,    g_H12);
    cudaGetSymbolAddress((void**)&x1_p,     g_x1);
    cudaGetSymbolAddress((void**)&ffnorm_p, g_ffnorm);
    cudaGetSymbolAddress((void**)&h3_p,     g_H3);
    cudaGetSymbolAddress((void**)&w1c_p,    g_w1cat);
    cudaGetSymbolAddress((void**)&w2c_p,    g_w2cat);
    cudaGetSymbolAddress((void**)&fw1_p,    g_ffw1h);
    cudaGetSymbolAddress((void**)&fw2_p,    g_ffw2h);
    cudaGetSymbolAddress((void**)&emb_p,    g_emb);
    cudaGetSymbolAddress((void**)&ffada_p,  g_ffada);

    dim3 thr(256);
    const int CB1 = (1024 * 1024 / 4 + 255) / 256;   // 1M elems
    const int CB2 = (1024 * 2048 / 4 + 255) / 256;   // 2M elems

    // weight conversions (fp32 -> fp16, with concatenation)
    convert_strided<<<CB1, thr>>>(w1c_p, ssm_w1, 1024, 1024, 2048, 0);
    convert_strided<<<CB1, thr>>>(w1c_p, bwd_w1, 1024, 1024, 2048, 1024);
    convert_strided<<<CB1, thr>>>(w2c_p,               ssm_w2, 1024, 1024, 1024, 0);
    convert_strided<<<CB1, thr>>>(w2c_p + 1024 * 1024, bwd_w2, 1024, 1024, 1024, 0);
    convert_strided<<<CB2, thr>>>(fw1_p, ff_w1, 1024, 2048, 2048, 0);
    convert_strided<<<CB2, thr>>>(fw2_p, ff_w2, 2048, 1024, 1024, 0);

    // adaLN vectors
    adaln_kernel<<<24, thr>>>(t, ada_w, ada_b, ffada_w, ffada_b, emb_p, ffada_p);

    // LN1 (masked, modulated)
    ln_mod_kernel<true><<<MROWS, thr>>>(x, emb_p, mask, norm_p);

    // GEMM1: H12 = gelu_erf(norm @ [ssm_w1|bwd_w1] + [b1;b1b])   16384x2048x1024
    gemm_f16<0><<<dim3(16, 128), thr>>>(norm_p, w1c_p, MROWS, 2048, 1024,
                                        ssm_b1, bwd_b1, 1024,
                                        nullptr, nullptr, nullptr, h12_p);

    // GEMM2: x1 = x + gate_msa * mask * (H12 @ [w2;w2b] + b2a + b2b)  16384x1024x2048
    gemm_f16<1><<<dim3(8, 128), thr>>>(h12_p, w2c_p, MROWS, 1024, 2048,
                                       ssm_b2, bwd_b2, 0,
                                       x, emb_p, mask, x1_p);

    // LN2 (unmasked, modulated)
    ln_mod_kernel<false><<<MROWS, thr>>>(x1_p, ffada_p, nullptr, ffnorm_p);

    // GEMM3: H3 = gelu_tanh(ffnorm @ ff_w1 + b1)   16384x2048x1024
    gemm_f16<2><<<dim3(16, 128), thr>>>(ffnorm_p, fw1_p, MROWS, 2048, 1024,
                                        ff_b1, ff_b1, 4096,
                                        nullptr, nullptr, nullptr, h3_p);

    // GEMM4: out = x1 + gate_mlp * (H3 @ ff_w2 + b2)   16384x1024x2048
    gemm_f16<3><<<dim3(8, 128), thr>>>(h3_p, fw2_p, MROWS, 1024, 2048,
                                       ff_b2, ff_b2, 0,
                                       x1_p, ffada_p, nullptr, out);
}

// round 7
// speedup vs baseline: 1.1524x; 1.1524x over previous
#include <cuda_runtime.h>
#include <cuda_fp16.h>
#include <cstdint>

// ---------------------------------------------------------------------------
// B=8, L=2048, D=1024, FF_MULT=2;  M = 16384
// ---------------------------------------------------------------------------
#define MROWS 16384
#define EPS_LN 1e-6f

// ---------------------------------------------------------------------------
// Scratch (device globals)
// ---------------------------------------------------------------------------
__device__ __half g_norm  [MROWS * 1024];
__device__ __half g_H12   [MROWS * 2048];
__device__ float  g_x1    [MROWS * 1024];
__device__ __half g_ffnorm[MROWS * 1024];
__device__ __half g_H3    [MROWS * 2048];
__device__ __half g_w1T   [2048 * 1024];   // [ssm_w1|bwd_w1]^T  (N=2048, K=1024) K-major
__device__ __half g_w2T   [1024 * 2048];   // [ssm_w2;bwd_w2]^T  (N=1024, K=2048)
__device__ __half g_ffw1T [2048 * 1024];   // ff_w1^T
__device__ __half g_ffw2T [1024 * 2048];   // ff_w2^T
__device__ float  g_emb   [8 * 3072];
__device__ float  g_ffada [8 * 3072];

// ---------------------------------------------------------------------------
// Helpers
// ---------------------------------------------------------------------------
__device__ __forceinline__ uint32_t smem_u32(const void* p) {
    return (uint32_t)__cvta_generic_to_shared(p);
}
__device__ __forceinline__ float gelu_erf_f(float x) {
    return 0.5f * x * (1.f + erff(x * 0.70710678118654752f));
}
__device__ __forceinline__ float gelu_tanh_f(float x) {
    float x3 = x * x * x;
    return 0.5f * x * (1.f + tanhf(0.79788456080286536f * (x + 0.044715f * x3)));
}
#define SWZ(off) ((off) ^ (((off) >> 3) & 0x70))

#define CP_ASYNC16(dst, src) \
    asm volatile("cp.async.cg.shared.global [%0], [%1], 16;" :: "r"(dst), "l"(src) : "memory")

// ---------------------------------------------------------------------------
// transpose + fp32->fp16:  dst[(n+rowOff)*dstStride + colOff + k] = src[k*N + n]
// block (32,8), grid (N/32, K/32)
// ---------------------------------------------------------------------------
__global__ void transpose_convert(__half* __restrict__ dst, const float* __restrict__ src,
                                  int N, int dstStride, int rowOff, int colOff)
{
    __shared__ float tile[32][33];
    int k0 = blockIdx.y * 32, n0 = blockIdx.x * 32;
    int tx = threadIdx.x, ty = threadIdx.y;
    #pragma unroll
    for (int j = 0; j < 4; j++)
        tile[ty + j * 8][tx] = src[(size_t)(k0 + ty + j * 8) * N + n0 + tx];
    __syncthreads();
    #pragma unroll
    for (int j = 0; j < 4; j++) {
        int n = n0 + ty + j * 8, k = k0 + tx;
        dst[(size_t)(n + rowOff) * dstStride + colOff + k] = __float2half(tile[tx][ty + j * 8]);
    }
}

// ---------------------------------------------------------------------------
// adaLN
// ---------------------------------------------------------------------------
__global__ __launch_bounds__(256)
void adaln_kernel(const float* __restrict__ t,
                  const float* __restrict__ ada_w,  const float* __restrict__ ada_b,
                  const float* __restrict__ ffada_w,const float* __restrict__ ffada_b,
                  float* __restrict__ emb, float* __restrict__ ffada)
{
    __shared__ float st[8][1024];
    int tid = threadIdx.x;
    for (int i = tid; i < 8 * 1024; i += 256) {
        float v = t[i];
        st[i >> 10][i & 1023] = v / (1.f + expf(-v));
    }
    __syncthreads();

    int col = blockIdx.x * 256 + tid;
    const float* W; const float* Bv; float* O; int c;
    if (col < 3072) { W = ada_w;   Bv = ada_b;   O = emb;   c = col; }
    else            { W = ffada_w; Bv = ffada_b; O = ffada; c = col - 3072; }

    float acc[8];
    #pragma unroll
    for (int b = 0; b < 8; b++) acc[b] = 0.f;
    #pragma unroll 4
    for (int k = 0; k < 1024; k++) {
        float wv = W[(size_t)k * 3072 + c];
        #pragma unroll
        for (int b = 0; b < 8; b++) acc[b] += st[b][k] * wv;
    }
    float bv = Bv[c];
    #pragma unroll
    for (int b = 0; b < 8; b++) O[b * 3072 + c] = acc[b] + bv;
}

// ---------------------------------------------------------------------------
// LN + adaLN modulation (mask is int32)
// ---------------------------------------------------------------------------
template<bool MASKED>
__global__ __launch_bounds__(256)
void ln_mod_kernel(const float* __restrict__ x, const float* __restrict__ ada,
                   const int* __restrict__ maskp, __half* __restrict__ out)
{
    int row = blockIdx.x;
    int tid = threadIdx.x;
    const float* xr = x + (size_t)row * 1024;
    float4 xv = ((const float4*)xr)[tid];
    float s = xv.x + xv.y + xv.z + xv.w;
    float q = xv.x * xv.x + xv.y * xv.y + xv.z * xv.z + xv.w * xv.w;
    #pragma unroll
    for (int o = 16; o; o >>= 1) {
        s += __shfl_xor_sync(0xffffffffu, s, o);
        q += __shfl_xor_sync(0xffffffffu, q, o);
    }
    __shared__ float ss[8], sq[8];
    __shared__ float mu_s, rs_s;
    int w = tid >> 5;
    if ((tid & 31) == 0) { ss[w] = s; sq[w] = q; }
    __syncthreads();
    if (tid == 0) {
        float S = 0.f, Q = 0.f;
        #pragma unroll
        for (int i = 0; i < 8; i++) { S += ss[i]; Q += sq[i]; }
        float mu = S * (1.f / 1024.f);
        float var = Q * (1.f / 1024.f) - mu * mu;
        mu_s = mu; rs_s = rsqrtf(var + EPS_LN);
    }
    __syncthreads();

    __half* orow = out + (size_t)row * 1024;
    if (MASKED && maskp[row] == 0) {
        ((uint2*)orow)[tid] = make_uint2(0u, 0u);
        return;
    }
    float mu = mu_s, rs = rs_s;
    int b = row >> 11;
    const float* shp = ada + b * 3072;
    int c = tid * 4;
    float4 sh4 = *(const float4*)(shp + c);
    float4 sc4 = *(const float4*)(shp + 1024 + c);
    float o0 = (xv.x - mu) * rs * (1.f + sc4.x) + sh4.x;
    float o1 = (xv.y - mu) * rs * (1.f + sc4.y) + sh4.y;
    float o2 = (xv.z - mu) * rs * (1.f + sc4.z) + sh4.z;
    float o3 = (xv.w - mu) * rs * (1.f + sc4.w) + sh4.w;
    *(__half2*)(orow + c)     = __floats2half2_rn(o0, o1);
    *(__half2*)(orow + c + 2) = __floats2half2_rn(o2, o3);
}

// ---------------------------------------------------------------------------
// fp16 mma.sync GEMM with cp.async 3-stage pipeline.
//   C[M,N] = epi(A[M,K] @ Bw[N,K]^T),  both operands K-major, SW128 swizzle.
// CTA tile 128x128, BK=64. 8 warps: wm=warp&3 (32 rows), wn=warp>>2 (64 cols).
// smem: stage s: A at s*16KB, B at 48KB + s*16KB;  total 96KB, 2 CTAs/SM.
// EPI: 0 gelu_erf(+split bias)->half | 1 mask,+b0+b1,gate,+resid->float
//      2 gelu_tanh(+b0)->half       | 3 +b0,gate,+resid->float
// ---------------------------------------------------------------------------
#define GSM_TOTAL 98304

__device__ __forceinline__ void issue_stage64(
    uint32_t sbase, const __half* __restrict__ A, const __half* __restrict__ Bw,
    int row0, int col0, int K, int buf, int chunk, int tid)
{
    int k0 = chunk * 64;
    uint32_t a_s = sbase + (uint32_t)buf * 16384u;
    uint32_t b_s = sbase + 49152u + (uint32_t)buf * 16384u;
    #pragma unroll
    for (int j = 0; j < 4; j++) {
        int lin = tid + j * 256;
        int r = lin >> 3, g = lin & 7;
        uint32_t off = (uint32_t)(r * 128 + g * 16);
        CP_ASYNC16(a_s + SWZ(off), A + (size_t)(row0 + r) * K + k0 + g * 8);
    }
    #pragma unroll
    for (int j = 0; j < 4; j++) {
        int lin = tid + j * 256;
        int r = lin >> 3, g = lin & 7;
        uint32_t off = (uint32_t)(r * 128 + g * 16);
        CP_ASYNC16(b_s + SWZ(off), Bw + (size_t)(col0 + r) * K + k0 + g * 8);
    }
    asm volatile("cp.async.commit_group;" ::: "memory");
}

template<int EPI>
__global__ __launch_bounds__(256, 2)
void gemm_f16(const __half* __restrict__ A, const __half* __restrict__ Bw,
              int N, int K,
              const float* __restrict__ bias0, const float* __restrict__ bias1, int bsplit,
              const float* __restrict__ resid, const float* __restrict__ ada,
              const int* __restrict__ maskp,
              void* __restrict__ outp)
{
    extern __shared__ char smem[];
    uint32_t sbase = smem_u32(smem);
    const int tid  = threadIdx.x;
    const int lane = tid & 31;
    const int warp = tid >> 5;
    const int wm = warp & 3;
    const int wn = warp >> 2;
    const int row0 = blockIdx.y * 128;
    const int col0 = blockIdx.x * 128;
    const int nk = K >> 6;

    float acc[2][8][4];
    #pragma unroll
    for (int i = 0; i < 2; i++)
        #pragma unroll
        for (int j = 0; j < 8; j++)
            #pragma unroll
            for (int v = 0; v < 4; v++) acc[i][j][v] = 0.f;

    // prologue: chunks 0,1
    issue_stage64(sbase, A, Bw, row0, col0, K, 0, 0, tid);
    issue_stage64(sbase, A, Bw, row0, col0, K, 1, 1, tid);

    // per-lane ldmatrix row/col components (halves)
    const int a_r  = wm * 32 + (lane & 15);
    const int a_c  = (lane >> 4) * 8;
    const int b_r  = wn * 64 + (lane & 7) + ((lane >> 4) << 3);
    const int b_c  = ((lane >> 3) & 1) * 8;

    for (int i = 0; i < nk; i++) {
        int s = i % 3;
        asm volatile("cp.async.wait_group 1;" ::: "memory");
        __syncthreads();
        if (i + 2 < nk) issue_stage64(sbase, A, Bw, row0, col0, K, (i + 2) % 3, i + 2, tid);
        else asm volatile("cp.async.commit_group;" ::: "memory");

        uint32_t a_sm = sbase + (uint32_t)s * 16384u;
        uint32_t b_sm = sbase + 49152u + (uint32_t)s * 16384u;

        #pragma unroll
        for (int kk = 0; kk < 64; kk += 16) {
            uint32_t aF[2][4];
            uint32_t bF[8][2];
            #pragma unroll
            for (int mi = 0; mi < 2; mi++) {
                uint32_t off = (uint32_t)((a_r + mi * 16) * 128 + (kk + a_c) * 2);
                uint32_t addr = a_sm + SWZ(off);
                asm volatile("ldmatrix.sync.aligned.m8n8.x4.shared.b16 {%0,%1,%2,%3}, [%4];"
                    : "=r"(aF[mi][0]), "=r"(aF[mi][1]), "=r"(aF[mi][2]), "=r"(aF[mi][3])
                    : "r"(addr));
            }
            #pragma unroll
            for (int nt = 0; nt < 4; nt++) {
                uint32_t off = (uint32_t)((b_r + nt * 16) * 128 + (kk + b_c) * 2);
                uint32_t addr = b_sm + SWZ(off);
                asm volatile("ldmatrix.sync.aligned.m8n8.x4.shared.b16 {%0,%1,%2,%3}, [%4];"
                    : "=r"(bF[2*nt][0]), "=r"(bF[2*nt][1]), "=r"(bF[2*nt+1][0]), "=r"(bF[2*nt+1][1])
                    : "r"(addr));
            }
            #pragma unroll
            for (int mi = 0; mi < 2; mi++)
                #pragma unroll
                for (int j = 0; j < 8; j++)
                    asm volatile(
                        "mma.sync.aligned.m16n8k16.row.col.f32.f16.f16.f32 "
                        "{%0,%1,%2,%3}, {%4,%5,%6,%7}, {%8,%9}, {%0,%1,%2,%3};"
                        : "+f"(acc[mi][j][0]), "+f"(acc[mi][j][1]),
                          "+f"(acc[mi][j][2]), "+f"(acc[mi][j][3])
                        : "r"(aF[mi][0]), "r"(aF[mi][1]), "r"(aF[mi][2]), "r"(aF[mi][3]),
                          "r"(bF[j][0]), "r"(bF[j][1]));
        }
        __syncthreads();
    }

    // ---------------- epilogue ----------------
    const int lr = lane >> 2;
    const int lc = (lane & 3) * 2;
    #pragma unroll
    for (int i = 0; i < 2; i++) {
        #pragma unroll
        for (int j = 0; j < 8; j++) {
            int col = col0 + wn * 64 + j * 8 + lc;
            #pragma unroll
            for (int h = 0; h < 2; h++) {
                int r = row0 + wm * 32 + i * 16 + lr + h * 8;
                float v0 = acc[i][j][h * 2 + 0];
                float v1 = acc[i][j][h * 2 + 1];
                if (EPI == 0 || EPI == 2) {
                    float b0 = (col     < bsplit) ? bias0[col]     : bias1[col - bsplit];
                    float b1 = (col + 1 < bsplit) ? bias0[col + 1] : bias1[col + 1 - bsplit];
                    v0 += b0; v1 += b1;
                    if (EPI == 0) { v0 = gelu_erf_f(v0);  v1 = gelu_erf_f(v1); }
                    else          { v0 = gelu_tanh_f(v0); v1 = gelu_tanh_f(v1); }
                    __half* o = (__half*)outp + (size_t)r * N + col;
                    *(__half2*)o = __floats2half2_rn(v0, v1);
                } else {
                    int bi = r >> 11;
                    float g0 = ada[bi * 3072 + 2048 + col];
                    float g1 = ada[bi * 3072 + 2048 + col + 1];
                    if (EPI == 1) {
                        v0 += bias0[col]     + bias1[col];
                        v1 += bias0[col + 1] + bias1[col + 1];
                        if (maskp[r] == 0) { v0 = 0.f; v1 = 0.f; }
                    } else {
                        v0 += bias0[col];
                        v1 += bias0[col + 1];
                    }
                    const float* rp = resid + (size_t)r * N + col;
                    float2 res;
                    res.x = rp[0] + g0 * v0;
                    res.y = rp[1] + g1 * v1;
                    *(float2*)((float*)outp + (size_t)r * N + col) = res;
                }
            }
        }
    }
}

// ---------------------------------------------------------------------------
// launch
// ---------------------------------------------------------------------------
extern "C" void kernel_launch(void* const* d_in, const int* in_sizes, int n_in,
                              void* d_out, int out_size)
{
    const float* x       = (const float*)d_in[0];
    const float* t       = (const float*)d_in[1];
    const int*   mask    = (const int*)d_in[2];
    const float* ada_w   = (const float*)d_in[3];
    const float* ada_b   = (const float*)d_in[4];
    const float* ssm_w1  = (const float*)d_in[5];
    const float* ssm_b1  = (const float*)d_in[6];
    const float* ssm_w2  = (const float*)d_in[7];
    const float* ssm_b2  = (const float*)d_in[8];
    const float* bwd_w1  = (const float*)d_in[9];
    const float* bwd_b1  = (const float*)d_in[10];
    const float* bwd_w2  = (const float*)d_in[11];
    const float* bwd_b2  = (const float*)d_in[12];
    const float* ffada_w = (const float*)d_in[13];
    const float* ffada_b = (const float*)d_in[14];
    const float* ff_w1   = (const float*)d_in[15];
    const float* ff_b1   = (const float*)d_in[16];
    const float* ff_w2   = (const float*)d_in[17];
    const float* ff_b2   = (const float*)d_in[18];
    float* out = (float*)d_out;

    __half *norm_p, *h12_p, *ffnorm_p, *h3_p, *w1T_p, *w2T_p, *fw1T_p, *fw2T_p;
    float  *x1_p, *emb_p, *ffada_p;
    cudaGetSymbolAddress((void**)&norm_p,   g_norm);
    cudaGetSymbolAddress((void**)&h12_p,    g_H12);
    cudaGetSymbolAddress((void**)&x1_p,     g_x1);
    cudaGetSymbolAddress((void**)&ffnorm_p, g_ffnorm);
    cudaGetSymbolAddress((void**)&h3_p,     g_H3);
    cudaGetSymbolAddress((void**)&w1T_p,    g_w1T);
    cudaGetSymbolAddress((void**)&w2T_p,    g_w2T);
    cudaGetSymbolAddress((void**)&fw1T_p,   g_ffw1T);
    cudaGetSymbolAddress((void**)&fw2T_p,   g_ffw2T);
    cudaGetSymbolAddress((void**)&emb_p,    g_emb);
    cudaGetSymbolAddress((void**)&ffada_p,  g_ffada);

    cudaFuncSetAttribute(gemm_f16<0>, cudaFuncAttributeMaxDynamicSharedMemorySize, GSM_TOTAL);
    cudaFuncSetAttribute(gemm_f16<1>, cudaFuncAttributeMaxDynamicSharedMemorySize, GSM_TOTAL);
    cudaFuncSetAttribute(gemm_f16<2>, cudaFuncAttributeMaxDynamicSharedMemorySize, GSM_TOTAL);
    cudaFuncSetAttribute(gemm_f16<3>, cudaFuncAttributeMaxDynamicSharedMemorySize, GSM_TOTAL);

    dim3 tb(32, 8);
    // weight transposes (fp32 -> fp16, concatenated, K-major)
    transpose_convert<<<dim3(32, 32), tb>>>(w1T_p,  ssm_w1, 1024, 1024, 0,    0);
    transpose_convert<<<dim3(32, 32), tb>>>(w1T_p,  bwd_w1, 1024, 1024, 1024, 0);
    transpose_convert<<<dim3(32, 32), tb>>>(w2T_p,  ssm_w2, 1024, 2048, 0,    0);
    transpose_convert<<<dim3(32, 32), tb>>>(w2T_p,  bwd_w2, 1024, 2048, 0,    1024);
    transpose_convert<<<dim3(64, 32), tb>>>(fw1T_p, ff_w1,  2048, 1024, 0,    0);
    transpose_convert<<<dim3(32, 64), tb>>>(fw2T_p, ff_w2,  1024, 2048, 0,    0);

    adaln_kernel<<<24, 256>>>(t, ada_w, ada_b, ffada_w, ffada_b, emb_p, ffada_p);

    ln_mod_kernel<true><<<MROWS, 256>>>(x, emb_p, mask, norm_p);

    // GEMM1: H12 = gelu_erf(norm @ [w1|w1b] + [b1;b1b])      16384x2048x1024
    gemm_f16<0><<<dim3(16, 128), 256, GSM_TOTAL>>>(norm_p, w1T_p, 2048, 1024,
                                                   ssm_b1, bwd_b1, 1024,
                                                   nullptr, nullptr, nullptr, h12_p);

    // GEMM2: x1 = x + gate_msa * mask * (H12 @ [w2;w2b] + b2a + b2b)   16384x1024x2048
    gemm_f16<1><<<dim3(8, 128), 256, GSM_TOTAL>>>(h12_p, w2T_p, 1024, 2048,
                                                  ssm_b2, bwd_b2, 0,
                                                  x, emb_p, mask, x1_p);

    ln_mod_kernel<false><<<MROWS, 256>>>(x1_p, ffada_p, nullptr, ffnorm_p);

    // GEMM3: H3 = gelu_tanh(ffnorm @ ff_w1 + b1)             16384x2048x1024
    gemm_f16<2><<<dim3(16, 128), 256, GSM_TOTAL>>>(ffnorm_p, fw1T_p, 2048, 1024,
                                                   ff_b1, ff_b1, 1 << 30,
                                                   nullptr, nullptr, nullptr, h3_p);

    // GEMM4: out = x1 + gate_mlp * (H3 @ ff_w2 + b2)         16384x1024x2048
    gemm_f16<3><<<dim3(8, 128), 256, GSM_TOTAL>>>(h3_p, fw2T_p, 1024, 2048,
                                                  ff_b2, ff_b2, 1 << 30,
                                                  x1_p, ffada_p, nullptr, out);
}

// round 8
// speedup vs baseline: 1.1618x; 1.0082x over previous
#include <cuda_runtime.h>
#include <cuda_fp16.h>
#include <cstdint>

// ---------------------------------------------------------------------------
// B=8, L=2048, D=1024, FF_MULT=2;  M = 16384
// ---------------------------------------------------------------------------
#define MROWS 16384
#define EPS_LN 1e-6f

// ---------------------------------------------------------------------------
// Scratch (device globals)
// ---------------------------------------------------------------------------
__device__ __half g_norm  [MROWS * 1024];
__device__ __half g_H12   [MROWS * 2048];
__device__ float  g_x1    [MROWS * 1024];
__device__ __half g_ffnorm[MROWS * 1024];
__device__ __half g_H3    [MROWS * 2048];
__device__ __half g_w1T   [2048 * 1024];   // [ssm_w1|bwd_w1]^T  (N=2048, K=1024) K-major
__device__ __half g_w2T   [1024 * 2048];   // [ssm_w2;bwd_w2]^T  (N=1024, K=2048)
__device__ __half g_ffw1T [2048 * 1024];   // ff_w1^T
__device__ __half g_ffw2T [1024 * 2048];   // ff_w2^T
__device__ float  g_emb   [8 * 3072];
__device__ float  g_ffada [8 * 3072];

// ---------------------------------------------------------------------------
// Helpers
// ---------------------------------------------------------------------------
__device__ __forceinline__ uint32_t smem_u32(const void* p) {
    return (uint32_t)__cvta_generic_to_shared(p);
}
__device__ __forceinline__ float gelu_erf_f(float x) {
    return 0.5f * x * (1.f + erff(x * 0.70710678118654752f));
}
__device__ __forceinline__ float gelu_tanh_f(float x) {
    float x3 = x * x * x;
    return 0.5f * x * (1.f + tanhf(0.79788456080286536f * (x + 0.044715f * x3)));
}
#define SWZ(off) ((off) ^ (((off) >> 3) & 0x70))

#define CP_ASYNC16(dst, src) \
    asm volatile("cp.async.cg.shared.global [%0], [%1], 16;" :: "r"(dst), "l"(src) : "memory")

// ---------------------------------------------------------------------------
// transpose + fp32->fp16:  dst[(n+rowOff)*dstStride + colOff + k] = src[k*N + n]
// ---------------------------------------------------------------------------
__global__ void transpose_convert(__half* __restrict__ dst, const float* __restrict__ src,
                                  int N, int dstStride, int rowOff, int colOff)
{
    __shared__ float tile[32][33];
    int k0 = blockIdx.y * 32, n0 = blockIdx.x * 32;
    int tx = threadIdx.x, ty = threadIdx.y;
    #pragma unroll
    for (int j = 0; j < 4; j++)
        tile[ty + j * 8][tx] = src[(size_t)(k0 + ty + j * 8) * N + n0 + tx];
    __syncthreads();
    #pragma unroll
    for (int j = 0; j < 4; j++) {
        int n = n0 + ty + j * 8, k = k0 + tx;
        dst[(size_t)(n + rowOff) * dstStride + colOff + k] = __float2half(tile[tx][ty + j * 8]);
    }
}

// ---------------------------------------------------------------------------
// adaLN
// ---------------------------------------------------------------------------
__global__ __launch_bounds__(256)
void adaln_kernel(const float* __restrict__ t,
                  const float* __restrict__ ada_w,  const float* __restrict__ ada_b,
                  const float* __restrict__ ffada_w,const float* __restrict__ ffada_b,
                  float* __restrict__ emb, float* __restrict__ ffada)
{
    __shared__ float st[8][1024];
    int tid = threadIdx.x;
    for (int i = tid; i < 8 * 1024; i += 256) {
        float v = t[i];
        st[i >> 10][i & 1023] = v / (1.f + expf(-v));
    }
    __syncthreads();

    int col = blockIdx.x * 256 + tid;
    const float* W; const float* Bv; float* O; int c;
    if (col < 3072) { W = ada_w;   Bv = ada_b;   O = emb;   c = col; }
    else            { W = ffada_w; Bv = ffada_b; O = ffada; c = col - 3072; }

    float acc[8];
    #pragma unroll
    for (int b = 0; b < 8; b++) acc[b] = 0.f;
    #pragma unroll 4
    for (int k = 0; k < 1024; k++) {
        float wv = W[(size_t)k * 3072 + c];
        #pragma unroll
        for (int b = 0; b < 8; b++) acc[b] += st[b][k] * wv;
    }
    float bv = Bv[c];
    #pragma unroll
    for (int b = 0; b < 8; b++) O[b * 3072 + c] = acc[b] + bv;
}

// ---------------------------------------------------------------------------
// LN + adaLN modulation (mask is int32)
// ---------------------------------------------------------------------------
template<bool MASKED>
__global__ __launch_bounds__(256)
void ln_mod_kernel(const float* __restrict__ x, const float* __restrict__ ada,
                   const int* __restrict__ maskp, __half* __restrict__ out)
{
    int row = blockIdx.x;
    int tid = threadIdx.x;
    const float* xr = x + (size_t)row * 1024;
    float4 xv = ((const float4*)xr)[tid];
    float s = xv.x + xv.y + xv.z + xv.w;
    float q = xv.x * xv.x + xv.y * xv.y + xv.z * xv.z + xv.w * xv.w;
    #pragma unroll
    for (int o = 16; o; o >>= 1) {
        s += __shfl_xor_sync(0xffffffffu, s, o);
        q += __shfl_xor_sync(0xffffffffu, q, o);
    }
    __shared__ float ss[8], sq[8];
    __shared__ float mu_s, rs_s;
    int w = tid >> 5;
    if ((tid & 31) == 0) { ss[w] = s; sq[w] = q; }
    __syncthreads();
    if (tid == 0) {
        float S = 0.f, Q = 0.f;
        #pragma unroll
        for (int i = 0; i < 8; i++) { S += ss[i]; Q += sq[i]; }
        float mu = S * (1.f / 1024.f);
        float var = Q * (1.f / 1024.f) - mu * mu;
        mu_s = mu; rs_s = rsqrtf(var + EPS_LN);
    }
    __syncthreads();

    __half* orow = out + (size_t)row * 1024;
    if (MASKED && maskp[row] == 0) {
        ((uint2*)orow)[tid] = make_uint2(0u, 0u);
        return;
    }
    float mu = mu_s, rs = rs_s;
    int b = row >> 11;
    const float* shp = ada + b * 3072;
    int c = tid * 4;
    float4 sh4 = *(const float4*)(shp + c);
    float4 sc4 = *(const float4*)(shp + 1024 + c);
    float o0 = (xv.x - mu) * rs * (1.f + sc4.x) + sh4.x;
    float o1 = (xv.y - mu) * rs * (1.f + sc4.y) + sh4.y;
    float o2 = (xv.z - mu) * rs * (1.f + sc4.z) + sh4.z;
    float o3 = (xv.w - mu) * rs * (1.f + sc4.w) + sh4.w;
    *(__half2*)(orow + c)     = __floats2half2_rn(o0, o1);
    *(__half2*)(orow + c + 2) = __floats2half2_rn(o2, o3);
}

// ---------------------------------------------------------------------------
// fp16 mma.sync GEMM, cp.async 3-stage, CTA tile 128x128, BK=64.
// 4 warps (128 thr), warp grid 2x2, warp tile 64x64 -> smem operand traffic
// 16KB per k16 per CTA (was 24KB), LDSM:HMMA = 8:32.
// Both operands K-major, SW128 swizzle.
// EPI: 0 gelu_erf(+split bias)->half | 1 mask,+b0+b1,gate,+resid->float
//      2 gelu_tanh(+b0)->half       | 3 +b0,gate,+resid->float
// ---------------------------------------------------------------------------
#define GSM_TOTAL 98304

__device__ __forceinline__ void issue_stage64(
    uint32_t sbase, const __half* __restrict__ A, const __half* __restrict__ Bw,
    int row0, int col0, int K, int buf, int chunk, int tid)
{
    int k0 = chunk * 64;
    uint32_t a_s = sbase + (uint32_t)buf * 16384u;
    uint32_t b_s = sbase + 49152u + (uint32_t)buf * 16384u;
    #pragma unroll
    for (int j = 0; j < 8; j++) {
        int lin = tid + j * 128;
        int r = lin >> 3, g = lin & 7;
        uint32_t off = (uint32_t)(r * 128 + g * 16);
        CP_ASYNC16(a_s + SWZ(off), A + (size_t)(row0 + r) * K + k0 + g * 8);
    }
    #pragma unroll
    for (int j = 0; j < 8; j++) {
        int lin = tid + j * 128;
        int r = lin >> 3, g = lin & 7;
        uint32_t off = (uint32_t)(r * 128 + g * 16);
        CP_ASYNC16(b_s + SWZ(off), Bw + (size_t)(col0 + r) * K + k0 + g * 8);
    }
    asm volatile("cp.async.commit_group;" ::: "memory");
}

template<int EPI>
__global__ __launch_bounds__(128, 2)
void gemm_f16(const __half* __restrict__ A, const __half* __restrict__ Bw,
              int N, int K,
              const float* __restrict__ bias0, const float* __restrict__ bias1, int bsplit,
              const float* __restrict__ resid, const float* __restrict__ ada,
              const int* __restrict__ maskp,
              void* __restrict__ outp)
{
    extern __shared__ char smem[];
    uint32_t sbase = smem_u32(smem);
    const int tid  = threadIdx.x;
    const int lane = tid & 31;
    const int warp = tid >> 5;
    const int wm = warp & 1;          // 0..1 -> 64 rows
    const int wn = warp >> 1;         // 0..1 -> 64 cols
    const int row0 = blockIdx.y * 128;
    const int col0 = blockIdx.x * 128;
    const int nk = K >> 6;

    float acc[4][8][4];
    #pragma unroll
    for (int i = 0; i < 4; i++)
        #pragma unroll
        for (int j = 0; j < 8; j++)
            #pragma unroll
            for (int v = 0; v < 4; v++) acc[i][j][v] = 0.f;

    issue_stage64(sbase, A, Bw, row0, col0, K, 0, 0, tid);
    issue_stage64(sbase, A, Bw, row0, col0, K, 1, 1, tid);

    const int a_r = wm * 64 + (lane & 15);
    const int a_c = (lane >> 4) * 8;
    const int b_r = wn * 64 + (lane & 7) + ((lane >> 4) << 3);
    const int b_c = ((lane >> 3) & 1) * 8;

    for (int i = 0; i < nk; i++) {
        int s = i % 3;
        asm volatile("cp.async.wait_group 1;" ::: "memory");
        __syncthreads();
        if (i + 2 < nk) issue_stage64(sbase, A, Bw, row0, col0, K, (i + 2) % 3, i + 2, tid);
        else asm volatile("cp.async.commit_group;" ::: "memory");

        uint32_t a_sm = sbase + (uint32_t)s * 16384u;
        uint32_t b_sm = sbase + 49152u + (uint32_t)s * 16384u;

        #pragma unroll
        for (int kk = 0; kk < 64; kk += 16) {
            uint32_t aF[4][4];
            uint32_t bF[8][2];
            #pragma unroll
            for (int mi = 0; mi < 4; mi++) {
                uint32_t off = (uint32_t)((a_r + mi * 16) * 128 + (kk + a_c) * 2);
                uint32_t addr = a_sm + SWZ(off);
                asm volatile("ldmatrix.sync.aligned.m8n8.x4.shared.b16 {%0,%1,%2,%3}, [%4];"
                    : "=r"(aF[mi][0]), "=r"(aF[mi][1]), "=r"(aF[mi][2]), "=r"(aF[mi][3])
                    : "r"(addr));
            }
            #pragma unroll
            for (int nt = 0; nt < 4; nt++) {
                uint32_t off = (uint32_t)((b_r + nt * 16) * 128 + (kk + b_c) * 2);
                uint32_t addr = b_sm + SWZ(off);
                asm volatile("ldmatrix.sync.aligned.m8n8.x4.shared.b16 {%0,%1,%2,%3}, [%4];"
                    : "=r"(bF[2*nt][0]), "=r"(bF[2*nt][1]), "=r"(bF[2*nt+1][0]), "=r"(bF[2*nt+1][1])
                    : "r"(addr));
            }
            #pragma unroll
            for (int mi = 0; mi < 4; mi++)
                #pragma unroll
                for (int j = 0; j < 8; j++)
                    asm volatile(
                        "mma.sync.aligned.m16n8k16.row.col.f32.f16.f16.f32 "
                        "{%0,%1,%2,%3}, {%4,%5,%6,%7}, {%8,%9}, {%0,%1,%2,%3};"
                        : "+f"(acc[mi][j][0]), "+f"(acc[mi][j][1]),
                          "+f"(acc[mi][j][2]), "+f"(acc[mi][j][3])
                        : "r"(aF[mi][0]), "r"(aF[mi][1]), "r"(aF[mi][2]), "r"(aF[mi][3]),
                          "r"(bF[j][0]), "r"(bF[j][1]));
        }
        __syncthreads();
    }

    // ---------------- epilogue ----------------
    const int lr = lane >> 2;
    const int lc = (lane & 3) * 2;
    #pragma unroll
    for (int i = 0; i < 4; i++) {
        #pragma unroll
        for (int j = 0; j < 8; j++) {
            int col = col0 + wn * 64 + j * 8 + lc;
            #pragma unroll
            for (int h = 0; h < 2; h++) {
                int r = row0 + wm * 64 + i * 16 + lr + h * 8;
                float v0 = acc[i][j][h * 2 + 0];
                float v1 = acc[i][j][h * 2 + 1];
                if (EPI == 0 || EPI == 2) {
                    float b0 = (col     < bsplit) ? bias0[col]     : bias1[col - bsplit];
                    float b1 = (col + 1 < bsplit) ? bias0[col + 1] : bias1[col + 1 - bsplit];
                    v0 += b0; v1 += b1;
                    if (EPI == 0) { v0 = gelu_erf_f(v0);  v1 = gelu_erf_f(v1); }
                    else          { v0 = gelu_tanh_f(v0); v1 = gelu_tanh_f(v1); }
                    __half* o = (__half*)outp + (size_t)r * N + col;
                    *(__half2*)o = __floats2half2_rn(v0, v1);
                } else {
                    int bi = r >> 11;
                    float g0 = ada[bi * 3072 + 2048 + col];
                    float g1 = ada[bi * 3072 + 2048 + col + 1];
                    if (EPI == 1) {
                        v0 += bias0[col]     + bias1[col];
                        v1 += bias0[col + 1] + bias1[col + 1];
                        if (maskp[r] == 0) { v0 = 0.f; v1 = 0.f; }
                    } else {
                        v0 += bias0[col];
                        v1 += bias0[col + 1];
                    }
                    const float* rp = resid + (size_t)r * N + col;
                    float2 res;
                    res.x = rp[0] + g0 * v0;
                    res.y = rp[1] + g1 * v1;
                    *(float2*)((float*)outp + (size_t)r * N + col) = res;
                }
            }
        }
    }
}

// ---------------------------------------------------------------------------
// launch
// ---------------------------------------------------------------------------
extern "C" void kernel_launch(void* const* d_in, const int* in_sizes, int n_in,
                              void* d_out, int out_size)
{
    const float* x       = (const float*)d_in[0];
    const float* t       = (const float*)d_in[1];
    const int*   mask    = (const int*)d_in[2];
    const float* ada_w   = (const float*)d_in[3];
    const float* ada_b   = (const float*)d_in[4];
    const float* ssm_w1  = (const float*)d_in[5];
    const float* ssm_b1  = (const float*)d_in[6];
    const float* ssm_w2  = (const float*)d_in[7];
    const float* ssm_b2  = (const float*)d_in[8];
    const float* bwd_w1  = (const float*)d_in[9];
    const float* bwd_b1  = (const float*)d_in[10];
    const float* bwd_w2  = (const float*)d_in[11];
    const float* bwd_b2  = (const float*)d_in[12];
    const float* ffada_w = (const float*)d_in[13];
    const float* ffada_b = (const float*)d_in[14];
    const float* ff_w1   = (const float*)d_in[15];
    const float* ff_b1   = (const float*)d_in[16];
    const float* ff_w2   = (const float*)d_in[17];
    const float* ff_b2   = (const float*)d_in[18];
    float* out = (float*)d_out;

    __half *norm_p, *h12_p, *ffnorm_p, *h3_p, *w1T_p, *w2T_p, *fw1T_p, *fw2T_p;
    float  *x1_p, *emb_p, *ffada_p;
    cudaGetSymbolAddress((void**)&norm_p,   g_norm);
    cudaGetSymbolAddress((void**)&h12_p,    g_H12);
    cudaGetSymbolAddress((void**)&x1_p,     g_x1);
    cudaGetSymbolAddress((void**)&ffnorm_p, g_ffnorm);
    cudaGetSymbolAddress((void**)&h3_p,     g_H3);
    cudaGetSymbolAddress((void**)&w1T_p,    g_w1T);
    cudaGetSymbolAddress((void**)&w2T_p,    g_w2T);
    cudaGetSymbolAddress((void**)&fw1T_p,   g_ffw1T);
    cudaGetSymbolAddress((void**)&fw2T_p,   g_ffw2T);
    cudaGetSymbolAddress((void**)&emb_p,    g_emb);
    cudaGetSymbolAddress((void**)&ffada_p,  g_ffada);

    cudaFuncSetAttribute(gemm_f16<0>, cudaFuncAttributeMaxDynamicSharedMemorySize, GSM_TOTAL);
    cudaFuncSetAttribute(gemm_f16<1>, cudaFuncAttributeMaxDynamicSharedMemorySize, GSM_TOTAL);
    cudaFuncSetAttribute(gemm_f16<2>, cudaFuncAttributeMaxDynamicSharedMemorySize, GSM_TOTAL);
    cudaFuncSetAttribute(gemm_f16<3>, cudaFuncAttributeMaxDynamicSharedMemorySize, GSM_TOTAL);

    dim3 tb(32, 8);
    transpose_convert<<<dim3(32, 32), tb>>>(w1T_p,  ssm_w1, 1024, 1024, 0,    0);
    transpose_convert<<<dim3(32, 32), tb>>>(w1T_p,  bwd_w1, 1024, 1024, 1024, 0);
    transpose_convert<<<dim3(32, 32), tb>>>(w2T_p,  ssm_w2, 1024, 2048, 0,    0);
    transpose_convert<<<dim3(32, 32), tb>>>(w2T_p,  bwd_w2, 1024, 2048, 0,    1024);
    transpose_convert<<<dim3(64, 32), tb>>>(fw1T_p, ff_w1,  2048, 1024, 0,    0);
    transpose_convert<<<dim3(32, 64), tb>>>(fw2T_p, ff_w2,  1024, 2048, 0,    0);

    adaln_kernel<<<24, 256>>>(t, ada_w, ada_b, ffada_w, ffada_b, emb_p, ffada_p);

    ln_mod_kernel<true><<<MROWS, 256>>>(x, emb_p, mask, norm_p);

    // GEMM1: H12 = gelu_erf(norm @ [w1|w1b] + [b1;b1b])      16384x2048x1024
    gemm_f16<0><<<dim3(16, 128), 128, GSM_TOTAL>>>(norm_p, w1T_p, 2048, 1024,
                                                   ssm_b1, bwd_b1, 1024,
                                                   nullptr, nullptr, nullptr, h12_p);

    // GEMM2: x1 = x + gate_msa * mask * (H12 @ [w2;w2b] + b2a + b2b)   16384x1024x2048
    gemm_f16<1><<<dim3(8, 128), 128, GSM_TOTAL>>>(h12_p, w2T_p, 1024, 2048,
                                                  ssm_b2, bwd_b2, 0,
                                                  x, emb_p, mask, x1_p);

    ln_mod_kernel<false><<<MROWS, 256>>>(x1_p, ffada_p, nullptr, ffnorm_p);

    // GEMM3: H3 = gelu_tanh(ffnorm @ ff_w1 + b1)             16384x2048x1024
    gemm_f16<2><<<dim3(16, 128), 128, GSM_TOTAL>>>(ffnorm_p, fw1T_p, 2048, 1024,
                                                   ff_b1, ff_b1, 1 << 30,
                                                   nullptr, nullptr, nullptr, h3_p);

    // GEMM4: out = x1 + gate_mlp * (H3 @ ff_w2 + b2)         16384x1024x2048
    gemm_f16<3><<<dim3(8, 128), 128, GSM_TOTAL>>>(h3_p, fw2T_p, 1024, 2048,
                                                  ff_b2, ff_b2, 1 << 30,
                                                  x1_p, ffada_p, nullptr, out);
}